// round 3
// baseline (speedup 1.0000x reference)
#include <cuda_runtime.h>
#include <cuda_fp16.h>
#include <math.h>

// ---------------- problem constants ----------------
#define L_    2
#define B_    32
#define T_    16
#define H_    1024
#define K_    2048          // concat(x,h) reduction dim
#define NCTA  64            // one M-tile of 64 gate rows per CTA
#define TM    64
#define NTHREADS 256
#define APITCH 72           // 64 + 8 halves  (144B rows, conflict-free ldmatrix)
#define XPITCH 40           // 32 + 8 halves  (80B rows,  conflict-free ldmatrix.trans)
#define RET_ELEMS (B_*T_*H_)

// smem layout (bytes)
#define SM_X   0                         // 2048*40 half   = 163840
#define SM_A   163840                    // 2*2*64*72 half =  36864
#define SM_G   200704                    // 64*33 float    =   8448
#define SM_C   209152                    // 2*16*32 float  =   4096
#define SM_H   213248                    // 2*16*32 float  =   4096
#define SM_R   217344                    // 256 float      =   1024
#define SMEM_TOTAL 218368

// ---------------- device globals (scratch; no allocs allowed) ----------------
__device__ __half  g_W[L_][NCTA][TM][K_];     // permuted fp16 weights (32 MB)
__device__ float   g_bias[L_][NCTA][TM];      // b_ih + b_hh, permuted
__device__ __half  g_xin[2][H_][B_];          // "out" input, parity by cell index
__device__ __half  g_hst[2][L_][H_][B_];      // per-layer h state, parity by t
__device__ float   g_losspart[NCTA];
__device__ unsigned g_bar;

// ---------------- helpers ----------------
__device__ __forceinline__ unsigned su(const void* p) {
    return (unsigned)__cvta_generic_to_shared(p);
}
__device__ __forceinline__ void cp16(unsigned d, const void* s) {
    asm volatile("cp.async.cg.shared.global [%0], [%1], 16;\n" :: "r"(d), "l"(s));
}
__device__ __forceinline__ void cpcommit() { asm volatile("cp.async.commit_group;\n"); }
__device__ __forceinline__ void cpwait0()  { asm volatile("cp.async.wait_group 0;\n"); }

__device__ __forceinline__ void ldsm4(unsigned* r, unsigned a) {
    asm volatile("ldmatrix.sync.aligned.m8n8.x4.shared.b16 {%0,%1,%2,%3}, [%4];\n"
                 : "=r"(r[0]), "=r"(r[1]), "=r"(r[2]), "=r"(r[3]) : "r"(a));
}
__device__ __forceinline__ void ldsm4t(unsigned* r, unsigned a) {
    asm volatile("ldmatrix.sync.aligned.m8n8.x4.trans.shared.b16 {%0,%1,%2,%3}, [%4];\n"
                 : "=r"(r[0]), "=r"(r[1]), "=r"(r[2]), "=r"(r[3]) : "r"(a));
}
__device__ __forceinline__ void mma16816(float* c, const unsigned* a, const unsigned* b) {
    asm volatile("mma.sync.aligned.m16n8k16.row.col.f32.f16.f16.f32 "
                 "{%0,%1,%2,%3}, {%4,%5,%6,%7}, {%8,%9}, {%0,%1,%2,%3};\n"
                 : "+f"(c[0]), "+f"(c[1]), "+f"(c[2]), "+f"(c[3])
                 : "r"(a[0]), "r"(a[1]), "r"(a[2]), "r"(a[3]), "r"(b[0]), "r"(b[1]));
}
__device__ __forceinline__ float sigm(float v) { return 1.f / (1.f + expf(-v)); }

// grid barrier: 64 CTAs all resident (218KB smem -> 1 CTA/SM). Monotone counter.
__device__ __forceinline__ void gbar(unsigned target) {
    __syncthreads();
    if (threadIdx.x == 0) {
        __threadfence();
        atomicAdd(&g_bar, 1u);
        unsigned v;
        do {
            asm volatile("ld.acquire.gpu.global.u32 %0, [%1];" : "=r"(v) : "l"(&g_bar));
        } while (v < target);
    }
    __syncthreads();
}

// ---------------- weight conversion / permutation ----------------
// g_W[l][m][gate*16+ul][k] = fp16( k<1024 ? W_ih[l][gate*1024+m*16+ul][k]
//                                         : W_hh[l][gate*1024+m*16+ul][k-1024] )
__global__ void convert_weights(const float* __restrict__ W_ih,
                                const float* __restrict__ W_hh) {
    const long total = (long)L_ * NCTA * TM * K_;   // 16,777,216
    for (long o = (long)blockIdx.x * blockDim.x + threadIdx.x; o < total;
         o += (long)gridDim.x * blockDim.x) {
        int k   = (int)(o & 2047);
        long r  = o >> 11;
        int row = (int)(r & 63);  r >>= 6;
        int m   = (int)(r & 63);  r >>= 6;
        int l   = (int)r;
        int gate = row >> 4, ul = row & 15;
        int srow = gate * 1024 + m * 16 + ul;
        float v = (k < 1024) ? W_ih[((long)l * 4096 + srow) * 1024 + k]
                             : W_hh[((long)l * 4096 + srow) * 1024 + (k - 1024)];
        ((__half*)g_W)[o] = __float2half(v);
    }
}

__global__ void init_state(const float* __restrict__ x, const float* __restrict__ h0,
                           const float* __restrict__ b_ih, const float* __restrict__ b_hh) {
    int tid0 = blockIdx.x * blockDim.x + threadIdx.x;
    int stride = gridDim.x * blockDim.x;
    if (tid0 == 0) g_bar = 0u;
    // g_xin[0][k][b] = x[b][k]
    for (int i = tid0; i < H_ * B_; i += stride) {
        int k = i >> 5, b = i & 31;
        g_xin[0][k][b] = __float2half(x[b * H_ + k]);
    }
    // g_hst[0][l][k][b] = h0[l][b][k]
    for (int i = tid0; i < L_ * H_ * B_; i += stride) {
        int b = i & 31, k = (i >> 5) & 1023, l = i >> 15;
        g_hst[0][l][k][b] = __float2half(h0[(l * B_ + b) * H_ + k]);
    }
    // g_bias[l][m][gate*16+ul] = b_ih + b_hh
    for (int i = tid0; i < L_ * NCTA * TM; i += stride) {
        int row = i & 63, m = (i >> 6) & 63, l = i >> 12;
        int gate = row >> 4, ul = row & 15;
        int sidx = l * 4096 + gate * 1024 + m * 16 + ul;
        g_bias[l][m][row] = b_ih[sidx] + b_hh[sidx];
    }
}

// ---------------- persistent LSTM kernel ----------------
__global__ void __launch_bounds__(NTHREADS, 1)
lstm_kernel(const float* __restrict__ c0,
            const float* __restrict__ h_mask, const float* __restrict__ c_mask,
            const float* __restrict__ labels, float* __restrict__ out, int write_loss) {
    const int m   = blockIdx.x;
    const int tid = threadIdx.x;
    const int w   = tid >> 5, lane = tid & 31;

    extern __shared__ char sm_[];
    __half* Xs    = (__half*)(sm_ + SM_X);   // [2048][XPITCH]
    __half* As    = (__half*)(sm_ + SM_A);   // [2 buf][2 khalf][64][APITCH]
    float*  gates = (float*)(sm_ + SM_G);    // [64][33]
    float*  cst   = (float*)(sm_ + SM_C);    // [2][16][32]
    float*  hst   = (float*)(sm_ + SM_H);
    float*  red   = (float*)(sm_ + SM_R);

    // init CTA-local fp32 state for its 16 units, both layers
    for (int i = tid; i < 2 * 16 * 32; i += NTHREADS) {
        int l = i >> 9, rem = i & 511, u = rem >> 5, b = rem & 31;
        int gu = m * 16 + u;
        cst[i] = c0[(l * B_ + b) * H_ + gu];
        // hst from g_hst (already fp16-rounded would lose bits) -> reload fp32 h0 path:
        // h0 not passed; instead reconstruct from global fp16 is lossy. We pass h0 via c0? No:
        hst[i] = 0.f;  // overwritten below
    }
    __syncthreads();
    // hst fp32 init: read back from g_hst fp16 would round; but zoneout "keep" path
    // uses h_old which at t=0 is h0 — rounding 5e-4 once is acceptable; still, use exact:
    // (we only have c0 pointer here; h0 exact values come through g_hst fp16.)
    for (int i = tid; i < 2 * 16 * 32; i += NTHREADS) {
        int l = i >> 9, rem = i & 511, u = rem >> 5, b = rem & 31;
        hst[i] = __half2float(g_hst[0][l][m * 16 + u][b]);
    }
    __syncthreads();

    const int khalf = w >> 2;             // 0: k[0,1024)   1: k[1024,2048)
    const int mrow  = (w & 3) * 16;       // warp's 16-row subtile
    const int aLaneRow = mrow + (lane & 15);
    const int aLaneCol = (lane >> 4) * 8;
    const int bLaneRow = (lane & 15);
    const int bLaneCol = (lane >> 4) * 8;

    float lossacc = 0.f;
    unsigned barcnt = 0;

    for (int n = 0; n < T_ * L_; n++) {
        const int t = n >> 1, l = n & 1;

        // ---- stage xh into smem: rows<1024 from g_xin[n&1], rest g_hst[t&1][l]
        const __half* srcx = &g_xin[n & 1][0][0];
        const __half* srch = &g_hst[t & 1][l][0][0];
        for (int c = tid; c < 8192; c += NTHREADS) {
            int row = c >> 2, seg = c & 3;
            const __half* src = (row < 1024) ? (srcx + row * 32 + seg * 8)
                                             : (srch + (row - 1024) * 32 + seg * 8);
            cp16(su(Xs + row * XPITCH + seg * 8), src);
        }
        cpcommit();

        // ---- chunk 0 of weights (both k-halves, 64 rows x 64 k each)
        const __half* Wb = &g_W[l][m][0][0];
        for (int c = tid; c < 1024; c += NTHREADS) {
            int h = c >> 9, rem = c & 511, r = rem >> 3, seg = rem & 7;
            cp16(su(As + ((0 * 2 + h) * 64 + r) * APITCH + seg * 8),
                 Wb + r * K_ + h * 1024 + 0 * 64 + seg * 8);
        }
        cpcommit();
        cpwait0();
        __syncthreads();

        // ---- GEMM: 16 chunk-steps of k64, double-buffered
        float acc[4][4];
#pragma unroll
        for (int j = 0; j < 4; j++)
#pragma unroll
            for (int q = 0; q < 4; q++) acc[j][q] = 0.f;

        for (int s = 0; s < 16; s++) {
            if (s + 1 < 16) {
                int sn = s + 1, buf = sn & 1;
                for (int c = tid; c < 1024; c += NTHREADS) {
                    int h = c >> 9, rem = c & 511, r = rem >> 3, seg = rem & 7;
                    cp16(su(As + ((buf * 2 + h) * 64 + r) * APITCH + seg * 8),
                         Wb + r * K_ + h * 1024 + sn * 64 + seg * 8);
                }
                cpcommit();
            }
            const int buf = s & 1;
            const unsigned aBase =
                su(As + ((buf * 2 + khalf) * 64 + aLaneRow) * APITCH + aLaneCol);
            const int kg = khalf * 1024 + s * 64;
#pragma unroll
            for (int kk = 0; kk < 4; kk++) {
                unsigned a[4], b0[4], b1[4];
                ldsm4(a, aBase + kk * 16 * 2);
                unsigned xb = su(Xs + (kg + kk * 16 + bLaneRow) * XPITCH + bLaneCol);
                ldsm4t(b0, xb);            // n cols 0..15
                ldsm4t(b1, xb + 16 * 2);   // n cols 16..31
                mma16816(acc[0], a, b0 + 0);
                mma16816(acc[1], a, b0 + 2);
                mma16816(acc[2], a, b1 + 0);
                mma16816(acc[3], a, b1 + 2);
            }
            if (s + 1 < 16) cpwait0();
            __syncthreads();
        }

        // ---- combine K-halves into gates smem
        if (khalf == 0) {
#pragma unroll
            for (int j = 0; j < 4; j++) {
                int col = j * 8 + (lane & 3) * 2;
                int r0 = mrow + (lane >> 2);
                gates[r0 * 33 + col]           = acc[j][0];
                gates[r0 * 33 + col + 1]       = acc[j][1];
                gates[(r0 + 8) * 33 + col]     = acc[j][2];
                gates[(r0 + 8) * 33 + col + 1] = acc[j][3];
            }
        }
        __syncthreads();
        if (khalf == 1) {
#pragma unroll
            for (int j = 0; j < 4; j++) {
                int col = j * 8 + (lane & 3) * 2;
                int r0 = mrow + (lane >> 2);
                gates[r0 * 33 + col]           += acc[j][0];
                gates[r0 * 33 + col + 1]       += acc[j][1];
                gates[(r0 + 8) * 33 + col]     += acc[j][2];
                gates[(r0 + 8) * 33 + col + 1] += acc[j][3];
            }
        }
        __syncthreads();

        // ---- elementwise: cell update + zoneout + publish h (fp16) + ret/loss
        {
            const int u = tid & 15, b0i = tid >> 4;
            const float* bia = g_bias[l][m];
            const float bi = bia[u], bf = bia[16 + u], bg = bia[32 + u], bo = bia[48 + u];
            const int gu = m * 16 + u;
            __half* oxin = g_xin[(n + 1) & 1][gu];
            __half* ohst = g_hst[(t & 1) ^ 1][l][gu];
#pragma unroll
            for (int bb = 0; bb < 2; bb++) {
                int b = b0i + bb * 16;
                float gi = gates[u * 33 + b]        + bi;
                float gf = gates[(16 + u) * 33 + b] + bf;
                float gg = gates[(32 + u) * 33 + b] + bg;
                float go = gates[(48 + u) * 33 + b] + bo;
                int   si = (l * 16 + u) * 32 + b;
                float cold = cst[si], hold = hst[si];
                float ccand = sigm(gf) * cold + sigm(gi) * tanhf(gg);
                float hcand = sigm(go) * tanhf(ccand);
                long  mo = ((long)((t * 2 + l) * 32 + b)) * 1024 + gu;
                float hm = h_mask[mo], cm = c_mask[mo];
                float cn = cm * cold + (1.f - cm) * ccand;
                float hn = hm * hold + (1.f - hm) * hcand;
                cst[si] = cn;
                hst[si] = hn;
                __half hh = __float2half(hn);
                oxin[b] = hh;
                ohst[b] = hh;
                if (l == 1) {
                    long ro = ((long)(b * T_ + t)) * 1024 + gu;
                    out[ro] = hn;
                    float d = hn - labels[ro];
                    lossacc += d * d;
                }
            }
        }
        barcnt += NCTA;
        gbar(barcnt);
    }

    // ---- deterministic loss reduction
    red[tid] = lossacc;
    __syncthreads();
    for (int sft = 128; sft > 0; sft >>= 1) {
        if (tid < sft) red[tid] += red[tid + sft];
        __syncthreads();
    }
    if (tid == 0) g_losspart[m] = red[0];
    barcnt += NCTA;
    gbar(barcnt);
    if (m == 0 && tid == 0 && write_loss) {
        float s = 0.f;
        for (int i = 0; i < NCTA; i++) s += g_losspart[i];
        out[RET_ELEMS] = s / (float)RET_ELEMS;
    }
}

// ---------------- launch ----------------
extern "C" void kernel_launch(void* const* d_in, const int* in_sizes, int n_in,
                              void* d_out, int out_size) {
    const float* x      = (const float*)d_in[0];
    const float* h0     = (const float*)d_in[1];
    const float* c0     = (const float*)d_in[2];
    const float* h_mask = (const float*)d_in[3];
    const float* c_mask = (const float*)d_in[4];
    const float* labels = (const float*)d_in[5];
    const float* W_ih   = (const float*)d_in[6];
    const float* W_hh   = (const float*)d_in[7];
    const float* b_ih   = (const float*)d_in[8];
    const float* b_hh   = (const float*)d_in[9];
    float* out = (float*)d_out;

    cudaFuncSetAttribute(lstm_kernel, cudaFuncAttributeMaxDynamicSharedMemorySize,
                         SMEM_TOTAL);

    init_state<<<64, 256>>>(x, h0, b_ih, b_hh);
    convert_weights<<<4096, 256>>>(W_ih, W_hh);
    int write_loss = (out_size > RET_ELEMS) ? 1 : 0;
    lstm_kernel<<<NCTA, NTHREADS, SMEM_TOTAL>>>(c0, h_mask, c_mask, labels, out,
                                                write_loss);
}

// round 4
// speedup vs baseline: 2.4820x; 2.4820x over previous
#include <cuda_runtime.h>
#include <cuda_fp16.h>
#include <math.h>

// ---------------- problem constants ----------------
#define L_    2
#define B_    32
#define T_    16
#define H_    1024
#define K_    2048
#define NCTA  128           // one 32-gate-row M-tile per CTA (8 units x 4 gates)
#define ROWS  32
#define NTHREADS 256
#define NW    8
#define KW    256           // K slice per warp
#define D_    6             // cp.async pipeline depth (stages of k16)
#define WP    24            // W stage pitch (halves): conflict-free ldmatrix
#define XP    40            // X stage pitch (halves): conflict-free ldmatrix.trans
#define RET_ELEMS (B_*T_*H_)

// smem layout (bytes)
#define SM_XB 0                                  // 8*6*16*40*2  = 61440
#define SM_WB (SM_XB + NW*D_*16*XP*2)            // 8*6*32*24*2  = 73728
#define SM_G  (SM_WB + NW*D_*ROWS*WP*2)          // 8*32*33*4    = 33792
#define SM_C  (SM_G + NW*ROWS*33*4)              // 2048
#define SM_H  (SM_C + 2048)                      // 2048
#define SM_R  (SM_H + 2048)                      // 1024
#define SMEM_TOTAL (SM_R + 1024)                 // 174080

// ---------------- device globals (scratch; no allocs) ----------------
__device__ __half  g_W[L_][NCTA][ROWS][K_];   // permuted fp16 weights (32 MB)
__device__ float   g_bias[L_][NCTA][ROWS];    // b_ih + b_hh, permuted
__device__ __half  g_xin[2][H_][B_];          // "out" chain input, parity by n
__device__ __half  g_hst[2][L_][H_][B_];      // per-layer h state, parity by t
__device__ float   g_losspart[NCTA];
__device__ unsigned g_bar;

// ---------------- helpers ----------------
__device__ __forceinline__ unsigned su(const void* p) {
    return (unsigned)__cvta_generic_to_shared(p);
}
__device__ __forceinline__ void cp16(unsigned d, const void* s) {
    asm volatile("cp.async.cg.shared.global [%0], [%1], 16;\n" :: "r"(d), "l"(s));
}
__device__ __forceinline__ void cpcommit() { asm volatile("cp.async.commit_group;\n"); }
template <int N>
__device__ __forceinline__ void cpwaitN() { asm volatile("cp.async.wait_group %0;\n" :: "n"(N)); }

__device__ __forceinline__ void ldsm4(unsigned* r, unsigned a) {
    asm volatile("ldmatrix.sync.aligned.m8n8.x4.shared.b16 {%0,%1,%2,%3}, [%4];\n"
                 : "=r"(r[0]), "=r"(r[1]), "=r"(r[2]), "=r"(r[3]) : "r"(a));
}
__device__ __forceinline__ void ldsm4t(unsigned* r, unsigned a) {
    asm volatile("ldmatrix.sync.aligned.m8n8.x4.trans.shared.b16 {%0,%1,%2,%3}, [%4];\n"
                 : "=r"(r[0]), "=r"(r[1]), "=r"(r[2]), "=r"(r[3]) : "r"(a));
}
__device__ __forceinline__ void mma16816(float* c, const unsigned* a, const unsigned* b) {
    asm volatile("mma.sync.aligned.m16n8k16.row.col.f32.f16.f16.f32 "
                 "{%0,%1,%2,%3}, {%4,%5,%6,%7}, {%8,%9}, {%0,%1,%2,%3};\n"
                 : "+f"(c[0]), "+f"(c[1]), "+f"(c[2]), "+f"(c[3])
                 : "r"(a[0]), "r"(a[1]), "r"(a[2]), "r"(a[3]), "r"(b[0]), "r"(b[1]));
}
__device__ __forceinline__ float sigm(float v) { return 1.f / (1.f + expf(-v)); }

// grid barrier: 128 CTAs, 174KB smem -> 1 CTA/SM, one wave on 152 SMs.
__device__ __forceinline__ void gbar(unsigned target) {
    __syncthreads();
    if (threadIdx.x == 0) {
        __threadfence();
        atomicAdd(&g_bar, 1u);
        unsigned v;
        do {
            asm volatile("ld.acquire.gpu.global.u32 %0, [%1];" : "=r"(v) : "l"(&g_bar));
        } while (v < target);
    }
    __syncthreads();
}

// ---------------- prep: weight convert + permute + state/bias init ----------------
// g_W[l][m][gate*8+u][k] = fp16( k<1024 ? W_ih[l][gate*1024+m*8+u][k]
//                                       : W_hh[l][gate*1024+m*8+u][k-1024] )
__global__ void prep(const float* __restrict__ x, const float* __restrict__ h0,
                     const float* __restrict__ W_ih, const float* __restrict__ W_hh,
                     const float* __restrict__ b_ih, const float* __restrict__ b_hh) {
    long tid0 = (long)blockIdx.x * blockDim.x + threadIdx.x;
    long stride = (long)gridDim.x * blockDim.x;
    if (tid0 == 0) g_bar = 0u;

    // weights: 8 consecutive halves per iter (vectorized 2x LDG.128 -> 1x STG.128)
    const long NV = (long)L_ * NCTA * ROWS * K_ / 8;   // 2,097,152
    for (long v = tid0; v < NV; v += stride) {
        long o = v << 3;
        int k   = (int)(o & (K_ - 1));
        int row = (int)((o >> 11) & 31);
        int m   = (int)((o >> 16) & 127);
        int l   = (int)(o >> 23);
        int srow = (row >> 3) * 1024 + m * 8 + (row & 7);
        const float* s = (k < 1024) ? W_ih + ((long)l * 4096 + srow) * 1024 + k
                                    : W_hh + ((long)l * 4096 + srow) * 1024 + (k - 1024);
        float4 f0 = ((const float4*)s)[0];
        float4 f1 = ((const float4*)s)[1];
        __half2 p0 = __floats2half2_rn(f0.x, f0.y);
        __half2 p1 = __floats2half2_rn(f0.z, f0.w);
        __half2 p2 = __floats2half2_rn(f1.x, f1.y);
        __half2 p3 = __floats2half2_rn(f1.z, f1.w);
        uint4 u;
        u.x = *reinterpret_cast<unsigned*>(&p0);
        u.y = *reinterpret_cast<unsigned*>(&p1);
        u.z = *reinterpret_cast<unsigned*>(&p2);
        u.w = *reinterpret_cast<unsigned*>(&p3);
        reinterpret_cast<uint4*>(g_W)[v] = u;
    }
    // g_xin[0][k][b] = x[b][k]
    for (long i = tid0; i < H_ * B_; i += stride) {
        int k = (int)(i >> 5), b = (int)(i & 31);
        g_xin[0][k][b] = __float2half(x[b * H_ + k]);
    }
    // g_hst[0][l][k][b] = h0[l][b][k]
    for (long i = tid0; i < (long)L_ * H_ * B_; i += stride) {
        int b = (int)(i & 31), k = (int)((i >> 5) & 1023), l = (int)(i >> 15);
        g_hst[0][l][k][b] = __float2half(h0[(l * B_ + b) * H_ + k]);
    }
    // g_bias[l][m][row]
    for (long i = tid0; i < (long)L_ * NCTA * ROWS; i += stride) {
        int row = (int)(i & 31), m = (int)((i >> 5) & 127), l = (int)(i >> 12);
        int sidx = l * 4096 + (row >> 3) * 1024 + m * 8 + (row & 7);
        g_bias[l][m][row] = b_ih[sidx] + b_hh[sidx];
    }
}

// ---------------- persistent LSTM kernel ----------------
__global__ void __launch_bounds__(NTHREADS, 1)
lstm_kernel(const float* __restrict__ c0, const float* __restrict__ h0,
            const float* __restrict__ h_mask, const float* __restrict__ c_mask,
            const float* __restrict__ labels, float* __restrict__ out, int write_loss) {
    const int m = blockIdx.x, tid = threadIdx.x;
    const int w = tid >> 5, lane = tid & 31;

    extern __shared__ char sm_[];
    __half* XB  = (__half*)(sm_ + SM_XB);
    __half* WBs = (__half*)(sm_ + SM_WB);
    float* part = (float*)(sm_ + SM_G);
    float* cst  = (float*)(sm_ + SM_C);
    float* hst  = (float*)(sm_ + SM_H);
    float* red  = (float*)(sm_ + SM_R);

    // exact fp32 state init for this CTA's 8 units, both layers
    for (int i = tid; i < 2 * 8 * 32; i += NTHREADS) {
        int l = i >> 8, u = (i >> 5) & 7, b = i & 31;
        int guu = m * 8 + u;
        cst[i] = c0[(l * B_ + b) * H_ + guu];
        hst[i] = h0[(l * B_ + b) * H_ + guu];
    }
    __syncthreads();

    const int k0 = w * KW;
    __half* XBw = XB  + w * D_ * 16 * XP;
    __half* WBw = WBs + w * D_ * ROWS * WP;
    const int aRow = lane & 15, aCol = (lane >> 4) * 8;

    float lossacc = 0.f;
    unsigned barcnt = 0;

    // pre-issue W stage copies for cell 0 (uncommitted; folded into first commit)
    {
        const __half* ws = &g_W[0][m][0][0] + k0;
#pragma unroll
        for (int st = 0; st < D_ - 1; st++)
#pragma unroll
            for (int j = 0; j < 2; j++) {
                int e = lane + 32 * j, r = e >> 1, sg = e & 1;
                cp16(su(WBw + (st * ROWS + r) * WP + sg * 8), ws + r * K_ + st * 16 + sg * 8);
            }
    }

    for (int n = 0; n < T_ * L_; n++) {
        const int t = n >> 1, l = n & 1;
        const __half* xsrc = (w < 4) ? &g_xin[n & 1][k0][0]
                                     : &g_hst[t & 1][l][k0 - 1024][0];

        // X prologue stages 0..D-2; commit st=0 also closes pre-issued W copies
#pragma unroll
        for (int st = 0; st < D_ - 1; st++) {
#pragma unroll
            for (int j = 0; j < 2; j++) {
                int e = lane + 32 * j, r = e >> 2, sg = e & 3;
                cp16(su(XBw + (st * 16 + r) * XP + sg * 8), xsrc + (st * 16 + r) * 32 + sg * 8);
            }
            cpcommit();
        }

        // prefetch masks (+labels) into regs; thread owns (u=w, b=lane)
        const int gu = m * 8 + w;
        const long mo = ((long)(n * B_ + lane)) * H_ + gu;
        const float hmv = __ldg(h_mask + mo);
        const float cmv = __ldg(c_mask + mo);
        float labv = 0.f;
        long ro = 0;
        if (l == 1) {
            ro = ((long)(lane * T_ + t)) * H_ + gu;
            labv = __ldg(labels + ro);
        }

        const __half* wsrc = &g_W[l][m][0][0] + k0;

        float acc0[4][4], acc1[4][4];
#pragma unroll
        for (int j = 0; j < 4; j++)
#pragma unroll
            for (int q = 0; q < 4; q++) { acc0[j][q] = 0.f; acc1[j][q] = 0.f; }

        // warp-private k16 pipeline: no CTA syncs inside
        for (int s = 0; s < 16; s++) {
            const int sp = s + D_ - 1;
            if (sp < 16) {
                const int p2 = sp % D_;
#pragma unroll
                for (int j = 0; j < 2; j++) {
                    int e = lane + 32 * j, r = e >> 2, sg = e & 3;
                    cp16(su(XBw + (p2 * 16 + r) * XP + sg * 8), xsrc + (sp * 16 + r) * 32 + sg * 8);
                }
#pragma unroll
                for (int j = 0; j < 2; j++) {
                    int e = lane + 32 * j, r = e >> 1, sg = e & 1;
                    cp16(su(WBw + (p2 * ROWS + r) * WP + sg * 8), wsrc + r * K_ + sp * 16 + sg * 8);
                }
            }
            cpcommit();
            cpwaitN<D_ - 1>();
            __syncwarp();

            const int p = s % D_;
            unsigned a0[4], a1[4], b0[4], b1[4];
            unsigned aB = su(WBw + (p * ROWS + aRow) * WP + aCol);
            ldsm4(a0, aB);
            ldsm4(a1, aB + 16 * WP * 2);
            unsigned xB_ = su(XBw + (p * 16 + aRow) * XP + aCol);
            ldsm4t(b0, xB_);
            ldsm4t(b1, xB_ + 32);
            mma16816(acc0[0], a0, b0 + 0); mma16816(acc0[1], a0, b0 + 2);
            mma16816(acc0[2], a0, b1 + 0); mma16816(acc0[3], a0, b1 + 2);
            mma16816(acc1[0], a1, b0 + 0); mma16816(acc1[1], a1, b0 + 2);
            mma16816(acc1[2], a1, b1 + 0); mma16816(acc1[3], a1, b1 + 2);
        }

        // partial gates to smem
#pragma unroll
        for (int f = 0; f < 2; f++) {
            float (*ac)[4] = f ? acc1 : acc0;
#pragma unroll
            for (int j = 0; j < 4; j++) {
                int r0 = f * 16 + (lane >> 2), col = j * 8 + (lane & 3) * 2;
                part[(w * ROWS + r0) * 33 + col]         = ac[j][0];
                part[(w * ROWS + r0) * 33 + col + 1]     = ac[j][1];
                part[(w * ROWS + r0 + 8) * 33 + col]     = ac[j][2];
                part[(w * ROWS + r0 + 8) * 33 + col + 1] = ac[j][3];
            }
        }
        __syncthreads();

        // cell math: thread (u=w, b=lane) — conflict-free smem reads, coalesced writes
        {
            const float* bia = g_bias[l][m];
            float g[4];
#pragma unroll
            for (int gg = 0; gg < 4; gg++) {
                float ssum = 0.f;
#pragma unroll
                for (int ww = 0; ww < 8; ww++)
                    ssum += part[(ww * ROWS + gg * 8 + w) * 33 + lane];
                g[gg] = ssum + bia[gg * 8 + w];
            }
            const int si = (l * 8 + w) * 32 + lane;
            float cold = cst[si], hold = hst[si];
            float ccand = sigm(g[1]) * cold + sigm(g[0]) * tanhf(g[2]);
            float hcand = sigm(g[3]) * tanhf(ccand);
            float cn = cmv * cold + (1.f - cmv) * ccand;
            float hn = hmv * hold + (1.f - hmv) * hcand;
            cst[si] = cn;
            hst[si] = hn;
            __half hh = __float2half(hn);
            g_xin[(n + 1) & 1][gu][lane] = hh;
            g_hst[(t & 1) ^ 1][l][gu][lane] = hh;
            if (l == 1) {
                out[ro] = hn;
                float d = hn - labv;
                lossacc += d * d;
            }
        }

        // pre-issue next cell's W stages (uncommitted) — transfers during barrier
        if (n + 1 < T_ * L_) {
            const __half* wn = &g_W[(n + 1) & 1][m][0][0] + k0;
#pragma unroll
            for (int st = 0; st < D_ - 1; st++)
#pragma unroll
                for (int j = 0; j < 2; j++) {
                    int e = lane + 32 * j, r = e >> 1, sg = e & 1;
                    cp16(su(WBw + (st * ROWS + r) * WP + sg * 8), wn + r * K_ + st * 16 + sg * 8);
                }
        }
        barcnt += NCTA;
        gbar(barcnt);
    }

    // deterministic loss reduction
    red[tid] = lossacc;
    __syncthreads();
    for (int sft = 128; sft > 0; sft >>= 1) {
        if (tid < sft) red[tid] += red[tid + sft];
        __syncthreads();
    }
    if (tid == 0) g_losspart[m] = red[0];
    barcnt += NCTA;
    gbar(barcnt);
    if (m == 0 && tid == 0 && write_loss) {
        float ssum = 0.f;
        for (int i = 0; i < NCTA; i++) ssum += g_losspart[i];
        out[RET_ELEMS] = ssum / (float)RET_ELEMS;
    }
}

// ---------------- launch ----------------
extern "C" void kernel_launch(void* const* d_in, const int* in_sizes, int n_in,
                              void* d_out, int out_size) {
    const float* x      = (const float*)d_in[0];
    const float* h0     = (const float*)d_in[1];
    const float* c0     = (const float*)d_in[2];
    const float* h_mask = (const float*)d_in[3];
    const float* c_mask = (const float*)d_in[4];
    const float* labels = (const float*)d_in[5];
    const float* W_ih   = (const float*)d_in[6];
    const float* W_hh   = (const float*)d_in[7];
    const float* b_ih   = (const float*)d_in[8];
    const float* b_hh   = (const float*)d_in[9];
    float* out = (float*)d_out;

    cudaFuncSetAttribute(lstm_kernel, cudaFuncAttributeMaxDynamicSharedMemorySize,
                         SMEM_TOTAL);

    prep<<<2048, 256>>>(x, h0, W_ih, W_hh, b_ih, b_hh);
    int write_loss = (out_size > RET_ELEMS) ? 1 : 0;
    lstm_kernel<<<NCTA, NTHREADS, SMEM_TOTAL>>>(c0, h0, h_mask, c_mask, labels, out,
                                                write_loss);
}

// round 5
// speedup vs baseline: 3.7999x; 1.5310x over previous
#include <cuda_runtime.h>
#include <cuda_fp16.h>
#include <math.h>

// ---------------- problem constants ----------------
#define L_    2
#define B_    32
#define T_    16
#define H_    1024
#define K_    2048
#define NCTA  128           // 32 gate rows per CTA (8 units x 4 gates)
#define ROWS  32
#define NTHREADS 256
#define KW    256           // K slice per warp
#define D_    5             // X cp.async pipeline depth (stages of k16)
#define XP    40            // X stage pitch in halves (conflict-free ldmatrix.trans)
#define RET_ELEMS (B_*T_*H_)

// smem layout (bytes)
#define SM_W1 0                         // 8 warps * 16KB resident layer-1 W = 131072
#define SM_XB 131072                    // 8 * 5 * 16 * 40 * 2 = 51200
#define SM_G  182272                    // 8*32*33*4 = 33792
#define SM_C  216064                    // 2048
#define SM_H  218112                    // 2048
#define SM_R  220160                    // 1024
#define SMEM_TOTAL 221184

// ---------------- device globals (scratch; no allocs) ----------------
__device__ __half  g_xin[2][H_][B_];          // chain input, parity by n
__device__ __half  g_hst[2][L_][H_][B_];      // per-layer h state, parity by t
__device__ float   g_losspart[NCTA];
__device__ unsigned g_bar;

// ---------------- helpers ----------------
__device__ __forceinline__ unsigned su(const void* p) {
    return (unsigned)__cvta_generic_to_shared(p);
}
__device__ __forceinline__ void cp16(unsigned d, const void* s) {
    asm volatile("cp.async.cg.shared.global [%0], [%1], 16;\n" :: "r"(d), "l"(s));
}
__device__ __forceinline__ void cpcommit() { asm volatile("cp.async.commit_group;\n"); }
template <int N>
__device__ __forceinline__ void cpwaitN() { asm volatile("cp.async.wait_group %0;\n" :: "n"(N)); }

__device__ __forceinline__ void ldsm4(unsigned* r, unsigned a) {
    asm volatile("ldmatrix.sync.aligned.m8n8.x4.shared.b16 {%0,%1,%2,%3}, [%4];\n"
                 : "=r"(r[0]), "=r"(r[1]), "=r"(r[2]), "=r"(r[3]) : "r"(a));
}
__device__ __forceinline__ void ldsm4t(unsigned* r, unsigned a) {
    asm volatile("ldmatrix.sync.aligned.m8n8.x4.trans.shared.b16 {%0,%1,%2,%3}, [%4];\n"
                 : "=r"(r[0]), "=r"(r[1]), "=r"(r[2]), "=r"(r[3]) : "r"(a));
}
__device__ __forceinline__ void mma16816(float* c, const unsigned* a, const unsigned* b) {
    asm volatile("mma.sync.aligned.m16n8k16.row.col.f32.f16.f16.f32 "
                 "{%0,%1,%2,%3}, {%4,%5,%6,%7}, {%8,%9}, {%0,%1,%2,%3};\n"
                 : "+f"(c[0]), "+f"(c[1]), "+f"(c[2]), "+f"(c[3])
                 : "r"(a[0]), "r"(a[1]), "r"(a[2]), "r"(a[3]), "r"(b[0]), "r"(b[1]));
}
__device__ __forceinline__ float sigm(float v) { return 1.f / (1.f + __expf(-v)); }

// grid barrier: 128 CTAs, 216KB smem -> 1 CTA/SM, one wave. Monotone counter.
__device__ __forceinline__ void gbar(unsigned target) {
    __syncthreads();
    if (threadIdx.x == 0) {
        asm volatile("red.release.gpu.global.add.u32 [%0], %1;\n"
                     :: "l"(&g_bar), "r"(1u));
        unsigned v;
        do {
            asm volatile("ld.acquire.gpu.global.u32 %0, [%1];" : "=r"(v) : "l"(&g_bar));
        } while (v < target);
    }
    __syncthreads();
}

// ---------------- prep: tiny (state transposes + barrier reset) ----------------
__global__ void prep(const float* __restrict__ x, const float* __restrict__ h0) {
    long tid0 = (long)blockIdx.x * blockDim.x + threadIdx.x;
    long stride = (long)gridDim.x * blockDim.x;
    if (tid0 == 0) g_bar = 0u;
    for (long i = tid0; i < H_ * B_; i += stride) {
        int k = (int)(i >> 5), b = (int)(i & 31);
        g_xin[0][k][b] = __float2half(x[b * H_ + k]);
    }
    for (long i = tid0; i < (long)L_ * H_ * B_; i += stride) {
        int b = (int)(i & 31), k = (int)((i >> 5) & 1023), l = (int)(i >> 15);
        g_hst[0][l][k][b] = __float2half(h0[(l * B_ + b) * H_ + k]);
    }
}

// ---------------- persistent LSTM kernel ----------------
__global__ void __launch_bounds__(NTHREADS, 1)
lstm_kernel(const float* __restrict__ c0, const float* __restrict__ h0,
            const float* __restrict__ h_mask, const float* __restrict__ c_mask,
            const float* __restrict__ labels,
            const float* __restrict__ W_ih, const float* __restrict__ W_hh,
            const float* __restrict__ b_ih, const float* __restrict__ b_hh,
            float* __restrict__ out, int write_loss) {
    const int m = blockIdx.x, tid = threadIdx.x;
    const int w = tid >> 5, lane = tid & 31;

    extern __shared__ char sm_[];
    __half* XB   = (__half*)(sm_ + SM_XB);
    float*  part = (float*)(sm_ + SM_G);
    float*  cst  = (float*)(sm_ + SM_C);
    float*  hst  = (float*)(sm_ + SM_H);
    float*  red  = (float*)(sm_ + SM_R);
    char*   W1w  = sm_ + SM_W1 + w * 16384;    // warp-private 16KB weight region

    // exact fp32 state init for this CTA's 8 units, both layers
    for (int i = tid; i < 2 * 8 * 32; i += NTHREADS) {
        int l = i >> 8, u = (i >> 5) & 7, b = i & 31;
        int guu = m * 8 + u;
        cst[i] = c0[(l * B_ + b) * H_ + guu];
        hst[i] = h0[(l * B_ + b) * H_ + guu];
    }

    // bias regs for thread's unit (u = w): br[l][gate]
    float br[2][4];
#pragma unroll
    for (int l = 0; l < 2; l++)
#pragma unroll
        for (int g = 0; g < 4; g++) {
            int idx = l * 4096 + g * 1024 + m * 8 + w;
            br[l][g] = b_ih[idx] + b_hh[idx];
        }

    const int k0 = w * KW;
    __half* XBw = XB + w * D_ * 16 * XP;
    const int aRow = lane & 15, aCol = (lane >> 4) * 8;
    const int aSel16 = (((lane >> 4) ^ ((aRow >> 2) & 1))) * 16;
    const unsigned wsu = su(W1w);
    const unsigned xsu = su(XBw);

    // ---- weight convert fp32->fp16 into swizzled layout (warp-private) ----
    // chunk (s,r,hf) @ byte off s*1024 + r*32 + (hf ^ ((r>>2)&1))*16 holds
    // row r, k = k0 + s*16 + hf*8 .. +8.
    unsigned aW0[16][4], aW1[16][4];   // layer-0 A fragments (RF-resident)
    {
        const int kb = (w & 3) * 256;
        const int s_ = lane >> 1, hf = lane & 1;
#pragma unroll 1
        for (int l = 0; l < 2; l++) {
            const float* Wsrc = (w < 4) ? (W_ih + (long)l * 4096 * 1024)
                                        : (W_hh + (long)l * 4096 * 1024);
#pragma unroll
            for (int i = 0; i < 32; i++) {
                int srow = (i >> 3) * 1024 + m * 8 + (i & 7);
                const float* src = Wsrc + (long)srow * 1024 + kb + s_ * 16 + hf * 8;
                float4 f0 = ((const float4*)src)[0];
                float4 f1 = ((const float4*)src)[1];
                __half2 p0 = __floats2half2_rn(f0.x, f0.y);
                __half2 p1 = __floats2half2_rn(f0.z, f0.w);
                __half2 p2 = __floats2half2_rn(f1.x, f1.y);
                __half2 p3 = __floats2half2_rn(f1.z, f1.w);
                uint4 u;
                u.x = *reinterpret_cast<unsigned*>(&p0);
                u.y = *reinterpret_cast<unsigned*>(&p1);
                u.z = *reinterpret_cast<unsigned*>(&p2);
                u.w = *reinterpret_cast<unsigned*>(&p3);
                *reinterpret_cast<uint4*>(
                    W1w + s_ * 1024 + i * 32 + (hf ^ ((i >> 2) & 1)) * 16) = u;
            }
            __syncwarp();
            if (l == 0) {   // pull layer-0 fragments into registers, then overwrite
#pragma unroll
                for (int s = 0; s < 16; s++) {
                    unsigned aB = wsu + s * 1024 + aRow * 32 + aSel16;
                    ldsm4(aW0[s], aB);
                    ldsm4(aW1[s], aB + 512);
                }
                __syncwarp();
            }
        }
    }
    __syncthreads();

    float lossacc = 0.f;
    unsigned barcnt = 0;

    for (int n = 0; n < T_ * L_; n++) {
        const int t = n >> 1, l = n & 1;
        const __half* xsrc = (w < 4) ? &g_xin[n & 1][k0][0]
                                     : &g_hst[t & 1][l][k0 - 1024][0];

        // X prologue: stages 0..D-2
#pragma unroll
        for (int st = 0; st < D_ - 1; st++) {
#pragma unroll
            for (int j = 0; j < 2; j++) {
                int e = lane + 32 * j, r = e >> 2, sg = e & 3;
                cp16(su(XBw + (st * 16 + r) * XP + sg * 8),
                     xsrc + (st * 16 + r) * 32 + sg * 8);
            }
            cpcommit();
        }

        // prefetch masks/labels for thread's (u=w, b=lane)
        const int gu = m * 8 + w;
        const long mo = ((long)(n * B_ + lane)) * H_ + gu;
        const float hmv = __ldg(h_mask + mo);
        const float cmv = __ldg(c_mask + mo);
        float labv = 0.f;
        long ro = 0;
        if (l == 1) {
            ro = ((long)(lane * T_ + t)) * H_ + gu;
            labv = __ldg(labels + ro);
        }

        float acc0[4][4], acc1[4][4];
#pragma unroll
        for (int j = 0; j < 4; j++)
#pragma unroll
            for (int q = 0; q < 4; q++) { acc0[j][q] = 0.f; acc1[j][q] = 0.f; }

        if (l == 0) {
            // A from registers
#pragma unroll
            for (int s = 0; s < 16; s++) {
                const int sp = s + D_ - 1;
                if (sp < 16) {
                    const int p2 = sp % D_;
#pragma unroll
                    for (int j = 0; j < 2; j++) {
                        int e = lane + 32 * j, r = e >> 2, sg = e & 3;
                        cp16(su(XBw + (p2 * 16 + r) * XP + sg * 8),
                             xsrc + (sp * 16 + r) * 32 + sg * 8);
                    }
                }
                cpcommit();
                cpwaitN<D_ - 1>();
                __syncwarp();
                const int p = s % D_;
                unsigned b0[4], b1[4];
                unsigned xB_ = xsu + ((p * 16 + aRow) * XP + aCol) * 2;
                ldsm4t(b0, xB_);
                ldsm4t(b1, xB_ + 32);
                mma16816(acc0[0], aW0[s], b0 + 0); mma16816(acc0[1], aW0[s], b0 + 2);
                mma16816(acc0[2], aW0[s], b1 + 0); mma16816(acc0[3], aW0[s], b1 + 2);
                mma16816(acc1[0], aW1[s], b0 + 0); mma16816(acc1[1], aW1[s], b0 + 2);
                mma16816(acc1[2], aW1[s], b1 + 0); mma16816(acc1[3], aW1[s], b1 + 2);
            }
        } else {
            // A from resident SMEM
#pragma unroll
            for (int s = 0; s < 16; s++) {
                const int sp = s + D_ - 1;
                if (sp < 16) {
                    const int p2 = sp % D_;
#pragma unroll
                    for (int j = 0; j < 2; j++) {
                        int e = lane + 32 * j, r = e >> 2, sg = e & 3;
                        cp16(su(XBw + (p2 * 16 + r) * XP + sg * 8),
                             xsrc + (sp * 16 + r) * 32 + sg * 8);
                    }
                }
                unsigned a0[4], a1[4];
                unsigned aB = wsu + s * 1024 + aRow * 32 + aSel16;
                ldsm4(a0, aB);
                ldsm4(a1, aB + 512);
                cpcommit();
                cpwaitN<D_ - 1>();
                __syncwarp();
                const int p = s % D_;
                unsigned b0[4], b1[4];
                unsigned xB_ = xsu + ((p * 16 + aRow) * XP + aCol) * 2;
                ldsm4t(b0, xB_);
                ldsm4t(b1, xB_ + 32);
                mma16816(acc0[0], a0, b0 + 0); mma16816(acc0[1], a0, b0 + 2);
                mma16816(acc0[2], a0, b1 + 0); mma16816(acc0[3], a0, b1 + 2);
                mma16816(acc1[0], a1, b0 + 0); mma16816(acc1[1], a1, b0 + 2);
                mma16816(acc1[2], a1, b1 + 0); mma16816(acc1[3], a1, b1 + 2);
            }
        }

        // partial gates to smem
#pragma unroll
        for (int f = 0; f < 2; f++) {
            float (*ac)[4] = f ? acc1 : acc0;
#pragma unroll
            for (int j = 0; j < 4; j++) {
                int r0 = f * 16 + (lane >> 2), col = j * 8 + (lane & 3) * 2;
                part[(w * ROWS + r0) * 33 + col]         = ac[j][0];
                part[(w * ROWS + r0) * 33 + col + 1]     = ac[j][1];
                part[(w * ROWS + r0 + 8) * 33 + col]     = ac[j][2];
                part[(w * ROWS + r0 + 8) * 33 + col + 1] = ac[j][3];
            }
        }
        __syncthreads();

        // cell math: thread (u=w, b=lane)
        {
            float g[4];
#pragma unroll
            for (int gg = 0; gg < 4; gg++) {
                float ssum = 0.f;
#pragma unroll
                for (int ww = 0; ww < 8; ww++)
                    ssum += part[(ww * ROWS + gg * 8 + w) * 33 + lane];
                g[gg] = ssum + br[l][gg];
            }
            const int si = (l * 8 + w) * 32 + lane;
            float cold = cst[si], hold = hst[si];
            float ccand = sigm(g[1]) * cold + sigm(g[0]) * tanhf(g[2]);
            float hcand = sigm(g[3]) * tanhf(ccand);
            float cn = cmv * cold + (1.f - cmv) * ccand;
            float hn = hmv * hold + (1.f - hmv) * hcand;
            cst[si] = cn;
            hst[si] = hn;
            __half hh = __float2half(hn);
            g_xin[(n + 1) & 1][gu][lane] = hh;
            g_hst[(t & 1) ^ 1][l][gu][lane] = hh;
            if (l == 1) {
                out[ro] = hn;
                float d = hn - labv;
                lossacc += d * d;
            }
        }

        barcnt += NCTA;
        gbar(barcnt);
    }

    // deterministic loss reduction
    red[tid] = lossacc;
    __syncthreads();
    for (int sft = 128; sft > 0; sft >>= 1) {
        if (tid < sft) red[tid] += red[tid + sft];
        __syncthreads();
    }
    if (tid == 0) g_losspart[m] = red[0];
    barcnt += NCTA;
    gbar(barcnt);
    if (m == 0 && tid == 0 && write_loss) {
        float ssum = 0.f;
        for (int i = 0; i < NCTA; i++) ssum += g_losspart[i];
        out[RET_ELEMS] = ssum / (float)RET_ELEMS;
    }
}

// ---------------- launch ----------------
extern "C" void kernel_launch(void* const* d_in, const int* in_sizes, int n_in,
                              void* d_out, int out_size) {
    const float* x      = (const float*)d_in[0];
    const float* h0     = (const float*)d_in[1];
    const float* c0     = (const float*)d_in[2];
    const float* h_mask = (const float*)d_in[3];
    const float* c_mask = (const float*)d_in[4];
    const float* labels = (const float*)d_in[5];
    const float* W_ih   = (const float*)d_in[6];
    const float* W_hh   = (const float*)d_in[7];
    const float* b_ih   = (const float*)d_in[8];
    const float* b_hh   = (const float*)d_in[9];
    float* out = (float*)d_out;

    cudaFuncSetAttribute(lstm_kernel, cudaFuncAttributeMaxDynamicSharedMemorySize,
                         SMEM_TOTAL);

    prep<<<128, 256>>>(x, h0);
    int write_loss = (out_size > RET_ELEMS) ? 1 : 0;
    lstm_kernel<<<NCTA, NTHREADS, SMEM_TOTAL>>>(c0, h0, h_mask, c_mask, labels,
                                                W_ih, W_hh, b_ih, b_hh, out,
                                                write_loss);
}